// round 2
// baseline (speedup 1.0000x reference)
#include <cuda_runtime.h>

#define N_TOKENS 8192
#define IN_CH    4096
#define OUT_CH   4096
#define RANK     16
#define KC       512                 // k-chunk staged in smem
#define NCHUNK   (IN_CH / KC)        // 8

typedef unsigned long long u64;

// scratch for t = x @ R^T : [8192, 16] fp32
__device__ float g_t[N_TOKENS * RANK];

__device__ __forceinline__ u64 f2fma(u64 a, u64 b, u64 c) {
    u64 d;
    asm("fma.rn.f32x2 %0, %1, %2, %3;" : "=l"(d) : "l"(a), "l"(b), "l"(c));
    return d;
}
__device__ __forceinline__ u64 splat2(float v) {
    u64 d;
    asm("mov.b64 %0, {%1, %1};" : "=l"(d) : "f"(v));
    return d;
}
__device__ __forceinline__ u64 pack2(float lo, float hi) {
    u64 d;
    asm("mov.b64 %0, {%1, %2};" : "=l"(d) : "f"(lo), "f"(hi));
    return d;
}

// ----------------------------------------------------------------------------
// Kernel 1: t[n, r] = sum_k x[n,k] * R[r,k]
// 256 thr = 8 warps. Warp pair shares 4 tokens; each warp does 8 of 16 ranks.
// acc = 4x8 u64 = 64 regs. R staged in smem chunks (32 KB), conflict-free
// LDS.128 reads. Per warp-iter: 8 LDS.128 (32 smem-cyc) vs 64 FFMA2
// (32 SMSP-cyc) -> pipes balanced.
// ----------------------------------------------------------------------------
__global__ void __launch_bounds__(256, 2)
k1_xRt(const float* __restrict__ x, const float* __restrict__ Rm) {
    __shared__ __align__(16) float Rs[RANK][KC];

    const int tid   = threadIdx.x;
    const int warp  = tid >> 5;
    const int lane  = tid & 31;
    const int tokg  = warp >> 1;             // 0..3
    const int rbase = (warp & 1) * 8;        // 0 or 8
    const int tok0  = blockIdx.x * 16 + tokg * 4;

    u64 acc[4][8];
#pragma unroll
    for (int tk = 0; tk < 4; tk++)
#pragma unroll
        for (int r = 0; r < 8; r++) acc[tk][r] = 0ull;

    const float* xr = x + (size_t)tok0 * IN_CH;

#pragma unroll 1
    for (int c = 0; c < NCHUNK; c++) {
        const int c0 = c * KC;
        __syncthreads();
        // stage R[0:16][c0:c0+KC] -> Rs. 2048 float4, 8 per thread, coalesced.
#pragma unroll
        for (int j = 0; j < 8; j++) {
            const int linear = tid + 256 * j;        // float4 index in tile
            const int row    = linear >> 7;          // KC/4 = 128 float4/row
            const int colf   = (linear & 127) << 2;  // float offset in row
            *reinterpret_cast<float4*>(&Rs[row][colf]) =
                *reinterpret_cast<const float4*>(&Rm[(size_t)row * IN_CH + c0 + colf]);
        }
        __syncthreads();

#pragma unroll
        for (int i = 0; i < KC / 128; i++) {         // 4 iters per chunk
            const int ks = i * 128 + lane * 4;       // smem float offset
            const int kf = c0 + ks;                  // gmem float offset
            ulonglong2 xv0 = *reinterpret_cast<const ulonglong2*>(&xr[0 * IN_CH + kf]);
            ulonglong2 xv1 = *reinterpret_cast<const ulonglong2*>(&xr[1 * IN_CH + kf]);
            ulonglong2 xv2 = *reinterpret_cast<const ulonglong2*>(&xr[2 * IN_CH + kf]);
            ulonglong2 xv3 = *reinterpret_cast<const ulonglong2*>(&xr[3 * IN_CH + kf]);
#pragma unroll
            for (int r = 0; r < 8; r++) {
                ulonglong2 rv = *reinterpret_cast<const ulonglong2*>(&Rs[rbase + r][ks]);
                acc[0][r] = f2fma(xv0.x, rv.x, acc[0][r]);
                acc[0][r] = f2fma(xv0.y, rv.y, acc[0][r]);
                acc[1][r] = f2fma(xv1.x, rv.x, acc[1][r]);
                acc[1][r] = f2fma(xv1.y, rv.y, acc[1][r]);
                acc[2][r] = f2fma(xv2.x, rv.x, acc[2][r]);
                acc[2][r] = f2fma(xv2.y, rv.y, acc[2][r]);
                acc[3][r] = f2fma(xv3.x, rv.x, acc[3][r]);
                acc[3][r] = f2fma(xv3.y, rv.y, acc[3][r]);
            }
        }
    }

    // cross-lane reduction; lane 0 writes this warp's 8-rank half of each row
#pragma unroll
    for (int tk = 0; tk < 4; tk++) {
        float s[8];
#pragma unroll
        for (int r = 0; r < 8; r++) {
            float2 v = *reinterpret_cast<float2*>(&acc[tk][r]);
            s[r] = v.x + v.y;
        }
#pragma unroll
        for (int off = 16; off > 0; off >>= 1) {
#pragma unroll
            for (int r = 0; r < 8; r++)
                s[r] += __shfl_xor_sync(0xffffffffu, s[r], off);
        }
        if (lane == 0) {
            float4* o = reinterpret_cast<float4*>(g_t + (size_t)(tok0 + tk) * RANK + rbase);
            o[0] = make_float4(s[0], s[1], s[2], s[3]);
            o[1] = make_float4(s[4], s[5], s[6], s[7]);
        }
    }
}

// ----------------------------------------------------------------------------
// Kernel 2: out[n, o] = bias[o] + sum_r t[n,r] * L[o,r]
// L held in REGISTERS (32 u64, packed for f32x2), loaded once per block.
// Block: 512 outputs x 128 tokens; t splatted into smem (16 KB), read as
// broadcast LDS.128 (8 per token vs 32 FFMA2 per token -> FMA/store bound).
// ----------------------------------------------------------------------------
__global__ void __launch_bounds__(128)
k2_tLt(const float* __restrict__ Lm, const float* __restrict__ bias,
       float* __restrict__ out) {
    __shared__ __align__(16) u64 ts2[128][16];   // splatted t

    const int tid     = threadIdx.x;
    const int bo      = blockIdx.x & 7;          // 8 o-chunks
    const int bt      = blockIdx.x >> 3;         // 64 token tiles
    const int obase   = bo * 512;
    const int tokbase = bt * 128;
    const int o4      = obase + tid * 4;

    // Load L[o4..o4+3][0..15] and transpose-pack into f32x2 registers:
    // Lp0[r] = (L[o4][r], L[o4+1][r]),  Lp1[r] = (L[o4+2][r], L[o4+3][r])
    u64 Lp0[16], Lp1[16];
    {
        float4 v[4][4];
#pragma unroll
        for (int i = 0; i < 4; i++) {
            const float4* lr = reinterpret_cast<const float4*>(Lm + (size_t)(o4 + i) * RANK);
            v[i][0] = lr[0]; v[i][1] = lr[1]; v[i][2] = lr[2]; v[i][3] = lr[3];
        }
#pragma unroll
        for (int q = 0; q < 4; q++) {
            Lp0[q * 4 + 0] = pack2(v[0][q].x, v[1][q].x);
            Lp0[q * 4 + 1] = pack2(v[0][q].y, v[1][q].y);
            Lp0[q * 4 + 2] = pack2(v[0][q].z, v[1][q].z);
            Lp0[q * 4 + 3] = pack2(v[0][q].w, v[1][q].w);
            Lp1[q * 4 + 0] = pack2(v[2][q].x, v[3][q].x);
            Lp1[q * 4 + 1] = pack2(v[2][q].y, v[3][q].y);
            Lp1[q * 4 + 2] = pack2(v[2][q].z, v[3][q].z);
            Lp1[q * 4 + 3] = pack2(v[2][q].w, v[3][q].w);
        }
    }
    const ulonglong2 bv = *reinterpret_cast<const ulonglong2*>(&bias[o4]);

    // stage splatted t: thread tid owns token tid's 16-float row
    {
        const float4* tp = reinterpret_cast<const float4*>(g_t + (size_t)(tokbase + tid) * RANK);
        float4 a = tp[0], b = tp[1], c = tp[2], d = tp[3];
        u64* dst = ts2[tid];
        dst[0]  = splat2(a.x); dst[1]  = splat2(a.y); dst[2]  = splat2(a.z); dst[3]  = splat2(a.w);
        dst[4]  = splat2(b.x); dst[5]  = splat2(b.y); dst[6]  = splat2(b.z); dst[7]  = splat2(b.w);
        dst[8]  = splat2(c.x); dst[9]  = splat2(c.y); dst[10] = splat2(c.z); dst[11] = splat2(c.w);
        dst[12] = splat2(d.x); dst[13] = splat2(d.y); dst[14] = splat2(d.z); dst[15] = splat2(d.w);
    }
    __syncthreads();

    float* outp = out + (size_t)tokbase * OUT_CH + o4;
#pragma unroll 4
    for (int tok = 0; tok < 128; tok++) {
        const ulonglong2* tp2 = reinterpret_cast<const ulonglong2*>(ts2[tok]);
        u64 a0 = bv.x, a1 = bv.y;
#pragma unroll
        for (int h = 0; h < 8; h++) {
            ulonglong2 t2 = tp2[h];                 // broadcast LDS.128
            a0 = f2fma(t2.x, Lp0[h * 2 + 0], a0);
            a1 = f2fma(t2.x, Lp1[h * 2 + 0], a1);
            a0 = f2fma(t2.y, Lp0[h * 2 + 1], a0);
            a1 = f2fma(t2.y, Lp1[h * 2 + 1], a1);
        }
        ulonglong2 o;
        o.x = a0; o.y = a1;
        *reinterpret_cast<ulonglong2*>(outp + (size_t)tok * OUT_CH) = o;
    }
}

extern "C" void kernel_launch(void* const* d_in, const int* in_sizes, int n_in,
                              void* d_out, int out_size) {
    (void)in_sizes; (void)n_in; (void)out_size;
    const float* x    = (const float*)d_in[0];   // [8192, 4096]
    const float* Lm   = (const float*)d_in[1];   // [4096, 16]
    const float* Rm   = (const float*)d_in[2];   // [16, 4096]
    const float* bias = (const float*)d_in[3];   // [4096]
    float* out = (float*)d_out;                  // [8192, 4096]

    k1_xRt<<<N_TOKENS / 16, 256>>>(x, Rm);
    k2_tLt<<<(N_TOKENS / 128) * (OUT_CH / 512), 128>>>(Lm, bias, out);
}